// round 1
// baseline (speedup 1.0000x reference)
#include <cuda_runtime.h>
#include <cstdint>

#define NN 100000
#define DF 64
#define NE 1600000

static constexpr float DTC   = 0.2f;
static constexpr float HALF_DT = 0.1f;
static constexpr float DT6   = 0.2f / 6.0f;

// ---------------- scratch (static device globals; no runtime allocation) ----------------
__device__ int   g_deg_r[NN];
__device__ int   g_deg_c[NN];
__device__ int   g_cursor[NN];
__device__ float g_dinv_r[NN];
__device__ float g_dinv_c[NN];
__device__ int   g_row_ptr[NN + 1];
__device__ int2  g_ew1[NE];   // (col, mask-folded weight bits)  -- first hop
__device__ int2  g_ew2[NE];   // (col, plain weight bits)        -- second hop
__device__ float g_u  [NN * DF];   // stage input buffer
__device__ float g_t1 [NN * DF];   // hop-1 intermediate
__device__ float g_acc[NN * DF];   // k1 + 2k2 + 2k3 (+k4 folded at the end)

// ---------------- preprocessing ----------------
__global__ void zero_kernel() {
    int i = blockIdx.x * blockDim.x + threadIdx.x;
    if (i < NN) { g_deg_r[i] = 0; g_deg_c[i] = 0; g_cursor[i] = 0; }
}

__global__ void hist_kernel(const int* __restrict__ row, const int* __restrict__ col) {
    int e = blockIdx.x * blockDim.x + threadIdx.x;
    if (e < NE) {
        atomicAdd(&g_deg_r[row[e]], 1);
        atomicAdd(&g_deg_c[col[e]], 1);
    }
}

__global__ void dinv_kernel() {
    int i = blockIdx.x * blockDim.x + threadIdx.x;
    if (i < NN) {
        int dr = g_deg_r[i];
        int dc = g_deg_c[i];
        g_dinv_r[i] = dr > 0 ? rsqrtf((float)dr) : 0.0f;
        g_dinv_c[i] = dc > 0 ? rsqrtf((float)dc) : 0.0f;
    }
}

// Single-block exclusive scan of g_deg_r -> g_row_ptr (N=100000, chunks of 1024).
__global__ void scan_kernel() {
    __shared__ int wsum[32];
    __shared__ int carry_s;
    int t = threadIdx.x, lane = t & 31, wid = t >> 5;
    if (t == 0) carry_s = 0;
    __syncthreads();
    for (int base = 0; base < NN; base += 1024) {
        int i = base + t;
        int v = (i < NN) ? g_deg_r[i] : 0;
        int incl = v;
        #pragma unroll
        for (int off = 1; off < 32; off <<= 1) {
            int x = __shfl_up_sync(0xffffffffu, incl, off);
            if (lane >= off) incl += x;
        }
        if (lane == 31) wsum[wid] = incl;
        __syncthreads();
        if (wid == 0) {
            int ws = wsum[lane];
            int wincl = ws;
            #pragma unroll
            for (int off = 1; off < 32; off <<= 1) {
                int x = __shfl_up_sync(0xffffffffu, wincl, off);
                if (lane >= off) wincl += x;
            }
            wsum[lane] = wincl - ws;   // exclusive offset of this warp
        }
        __syncthreads();
        int carry = carry_s;
        int excl = incl - v + wsum[wid];
        if (i < NN) g_row_ptr[i] = carry + excl;
        __syncthreads();
        if (t == 1023) carry_s = carry + excl + v;   // + block total
        __syncthreads();
    }
    if (threadIdx.x == 0) g_row_ptr[NN] = carry_s;
}

__global__ void scatter_kernel(const int* __restrict__ row, const int* __restrict__ col,
                               const int* __restrict__ mask) {
    int e = blockIdx.x * blockDim.x + threadIdx.x;
    if (e < NE) {
        int r = row[e];
        int c = col[e];
        int pos = g_row_ptr[r] + atomicAdd(&g_cursor[r], 1);
        float w = g_dinv_r[r] * g_dinv_c[c];
        g_ew2[pos] = make_int2(c, __float_as_int(w));
        g_ew1[pos] = make_int2(c, __float_as_int(mask[c] ? w : 0.0f));
    }
}

// ---------------- SpMM: warp per row, register accumulation ----------------
// MODE 0: hop-1: y = A_masked @ x  -> g_t1.   XU: 0 => x = xparam, 1 => x = g_u
// MODE 1 (k1): v = -(A @ t1); acc  = v;      u = r + 0.5*dt*v
// MODE 2 (k2): v = -(A @ t1); acc += 2v;     u = r + 0.5*dt*v
// MODE 3 (k3): v = -(A @ t1); acc += 2v;     u = r +     dt*v
// MODE 4 (k4): v = -(A @ t1); r_next = r + dt/6 * (acc + v)   (written to outparam)
template <int MODE, int XU>
__global__ void __launch_bounds__(256)
spmm_kernel(const float* __restrict__ xparam, const float* __restrict__ rin,
            float* __restrict__ outparam) {
    int wi = (blockIdx.x * blockDim.x + threadIdx.x) >> 5;
    if (wi >= NN) return;
    int lane = threadIdx.x & 31;

    const float* x = (MODE == 0) ? ((XU == 1) ? g_u : xparam) : g_t1;
    const int2* __restrict__ ew = (MODE == 0) ? g_ew1 : g_ew2;

    int s = g_row_ptr[wi];
    int e = g_row_ptr[wi + 1];

    float a0 = 0.0f, a1 = 0.0f;
    int i = s;
    for (; i + 1 < e; i += 2) {
        int2 p0 = ew[i];
        int2 p1 = ew[i + 1];
        const float* x0 = x + (size_t)p0.x * DF;
        const float* x1 = x + (size_t)p1.x * DF;
        float w0 = __int_as_float(p0.y);
        float w1 = __int_as_float(p1.y);
        float b00 = x0[lane], b01 = x0[lane + 32];
        float b10 = x1[lane], b11 = x1[lane + 32];
        a0 = fmaf(w0, b00, a0);
        a1 = fmaf(w0, b01, a1);
        a0 = fmaf(w1, b10, a0);
        a1 = fmaf(w1, b11, a1);
    }
    if (i < e) {
        int2 p = ew[i];
        const float* xr = x + (size_t)p.x * DF;
        float w = __int_as_float(p.y);
        a0 = fmaf(w, xr[lane], a0);
        a1 = fmaf(w, xr[lane + 32], a1);
    }

    int o = wi * DF + lane;
    if (MODE == 0) {
        g_t1[o] = a0;
        g_t1[o + 32] = a1;
        return;
    }
    float v0 = -a0, v1 = -a1;
    if (MODE == 1) {
        g_acc[o]      = v0;
        g_acc[o + 32] = v1;
        g_u[o]        = rin[o]      + HALF_DT * v0;
        g_u[o + 32]   = rin[o + 32] + HALF_DT * v1;
    } else if (MODE == 2) {
        g_acc[o]      += 2.0f * v0;
        g_acc[o + 32] += 2.0f * v1;
        g_u[o]        = rin[o]      + HALF_DT * v0;
        g_u[o + 32]   = rin[o + 32] + HALF_DT * v1;
    } else if (MODE == 3) {
        g_acc[o]      += 2.0f * v0;
        g_acc[o + 32] += 2.0f * v1;
        g_u[o]        = rin[o]      + DTC * v0;
        g_u[o + 32]   = rin[o + 32] + DTC * v1;
    } else {  // MODE == 4
        outparam[o]      = rin[o]      + DT6 * (g_acc[o]      + v0);
        outparam[o + 32] = rin[o + 32] + DT6 * (g_acc[o + 32] + v1);
    }
}

// ---------------- launch ----------------
extern "C" void kernel_launch(void* const* d_in, const int* in_sizes, int n_in,
                              void* d_out, int out_size) {
    const float* r0   = (const float*)d_in[0];
    const int*   eidx = (const int*)d_in[1];
    const int*   mask = (const int*)d_in[2];
    const int* row = eidx;
    const int* col = eidx + NE;
    float* out = (float*)d_out;

    // CSR build (per-call, graph-captured, deterministic work)
    zero_kernel   <<<(NN + 255) / 256, 256>>>();
    hist_kernel   <<<(NE + 255) / 256, 256>>>(row, col);
    dinv_kernel   <<<(NN + 255) / 256, 256>>>();
    scan_kernel   <<<1, 1024>>>();
    scatter_kernel<<<(NE + 255) / 256, 256>>>(row, col, mask);

    // slice 0 = r0
    cudaMemcpyAsync(out, r0, (size_t)NN * DF * sizeof(float),
                    cudaMemcpyDeviceToDevice, 0);

    const int blocks = (NN * 32 + 255) / 256;  // warp per row

    for (int step = 0; step < 5; step++) {
        const float* r  = out + (size_t)step * NN * DF;
        float* rnext    = out + (size_t)(step + 1) * NN * DF;

        // k1
        spmm_kernel<0, 0><<<blocks, 256>>>(r, nullptr, nullptr);
        spmm_kernel<1, 0><<<blocks, 256>>>(nullptr, r, nullptr);
        // k2
        spmm_kernel<0, 1><<<blocks, 256>>>(nullptr, nullptr, nullptr);
        spmm_kernel<2, 0><<<blocks, 256>>>(nullptr, r, nullptr);
        // k3
        spmm_kernel<0, 1><<<blocks, 256>>>(nullptr, nullptr, nullptr);
        spmm_kernel<3, 0><<<blocks, 256>>>(nullptr, r, nullptr);
        // k4 -> next state slice
        spmm_kernel<0, 1><<<blocks, 256>>>(nullptr, nullptr, nullptr);
        spmm_kernel<4, 0><<<blocks, 256>>>(nullptr, r, rnext);
    }
}

// round 2
// speedup vs baseline: 1.1872x; 1.1872x over previous
#include <cuda_runtime.h>
#include <cuda_fp16.h>
#include <cstdint>

#define NN 100000
#define DF 64
#define NE 1600000
#define NB ((NN + 1023) / 1024)   // 98 scan blocks

static constexpr float DTC     = 0.2f;
static constexpr float HALF_DT = 0.1f;
static constexpr float DT6     = 0.2f / 6.0f;

// ---------------- scratch (static device globals) ----------------
__device__ int     g_deg_r[NN];
__device__ int     g_deg_c[NN];
__device__ int     g_cursor[NN];
__device__ float   g_dinv_r[NN];        // row factor (applied to warp sum)
__device__ float   g_premul[NN];        // mask * dinv_c  (folded into stage input u)
__device__ float   g_dd[NN];            // dinv_r * dinv_c (folded into t1 store)
__device__ int     g_row_ptr[NN + 1];
__device__ int     g_part[NB];
__device__ int     g_ecol[NE];          // CSR column indices (shared by both hops)
__device__ __half2 g_uh [NN * DF / 2];  // stage input, premultiplied by mask*dinv_c, fp16
__device__ __half2 g_t1h[NN * DF / 2];  // hop-1 output, premultiplied by dinv_c, fp16
__device__ float2  g_acc[NN * DF / 2];  // k1 + 2k2 + 2k3

// ---------------- preprocessing ----------------
__global__ void zero_kernel() {
    int i = blockIdx.x * blockDim.x + threadIdx.x;
    if (i < NN) { g_deg_r[i] = 0; g_deg_c[i] = 0; g_cursor[i] = 0; }
}

__global__ void hist_kernel(const int* __restrict__ row, const int* __restrict__ col) {
    int e = blockIdx.x * blockDim.x + threadIdx.x;
    if (e < NE) {
        atomicAdd(&g_deg_r[row[e]], 1);
        atomicAdd(&g_deg_c[col[e]], 1);
    }
}

__global__ void dinv_kernel(const int* __restrict__ mask) {
    int i = blockIdx.x * blockDim.x + threadIdx.x;
    if (i < NN) {
        int dr = g_deg_r[i];
        int dc = g_deg_c[i];
        float ir = dr > 0 ? rsqrtf((float)dr) : 0.0f;
        float ic = dc > 0 ? rsqrtf((float)dc) : 0.0f;
        g_dinv_r[i] = ir;
        g_premul[i] = mask[i] ? ic : 0.0f;
        g_dd[i]     = ir * ic;
    }
}

// Two-level scan of g_deg_r -> g_row_ptr
__global__ void scan_block_kernel() {
    __shared__ int wsum[32];
    int b = blockIdx.x, t = threadIdx.x, lane = t & 31, wid = t >> 5;
    int i = b * 1024 + t;
    int v = (i < NN) ? g_deg_r[i] : 0;
    int incl = v;
    #pragma unroll
    for (int off = 1; off < 32; off <<= 1) {
        int x = __shfl_up_sync(0xffffffffu, incl, off);
        if (lane >= off) incl += x;
    }
    if (lane == 31) wsum[wid] = incl;
    __syncthreads();
    if (wid == 0) {
        int ws = wsum[lane];
        int wincl = ws;
        #pragma unroll
        for (int off = 1; off < 32; off <<= 1) {
            int x = __shfl_up_sync(0xffffffffu, wincl, off);
            if (lane >= off) wincl += x;
        }
        wsum[lane] = wincl - ws;
    }
    __syncthreads();
    int excl = incl - v + wsum[wid];
    if (i < NN) g_row_ptr[i] = excl;
    if (t == 1023) g_part[b] = excl + v;
}

__global__ void scan_part_kernel() {
    if (threadIdx.x == 0) {
        int s = 0;
        for (int b = 0; b < NB; b++) { int v = g_part[b]; g_part[b] = s; s += v; }
    }
}

__global__ void scan_add_kernel() {
    int i = blockIdx.x * 1024 + threadIdx.x;
    if (i < NN) g_row_ptr[i] += g_part[blockIdx.x];
    if (i == 0) g_row_ptr[NN] = NE;
}

__global__ void scatter_kernel(const int* __restrict__ row, const int* __restrict__ col) {
    int e = blockIdx.x * blockDim.x + threadIdx.x;
    if (e < NE) {
        int r = row[e];
        int pos = g_row_ptr[r] + atomicAdd(&g_cursor[r], 1);
        g_ecol[pos] = col[e];
    }
}

// uh = mask*dinv_c * r0  (fp16), one float2 per thread
__global__ void init_u_kernel(const float* __restrict__ r0) {
    int i = blockIdx.x * blockDim.x + threadIdx.x;   // float2 index
    if (i < NN * DF / 2) {
        int node = i >> 5;
        float p = g_premul[node];
        float2 r = ((const float2*)r0)[i];
        g_uh[i] = __floats2half2_rn(p * r.x, p * r.y);
    }
}

// ---------------- gather core: warp per row ----------------
__device__ __forceinline__ float2
row_gather(const __half2* __restrict__ x, int s, int e, int lane) {
    float a0 = 0.0f, a1 = 0.0f;
    for (int base = s; base < e; base += 32) {
        int idx = base + lane;
        int c = (idx < e) ? __ldg(&g_ecol[idx]) : 0;
        int n = min(32, e - base);
        #pragma unroll 4
        for (int j = 0; j < n; j++) {
            int cj = __shfl_sync(0xffffffffu, c, j);
            float2 f = __half22float2(__ldg(&x[cj * (DF / 2) + lane]));
            a0 += f.x;
            a1 += f.y;
        }
    }
    return make_float2(a0, a1);
}

// hop-1: t1h[i] = dinv_r[i]*dinv_c[i] * sum_e uh[col_e]
__global__ void __launch_bounds__(256)
hop1_kernel() {
    int wi = (blockIdx.x * blockDim.x + threadIdx.x) >> 5;
    if (wi >= NN) return;
    int lane = threadIdx.x & 31;
    float2 sum = row_gather(g_uh, g_row_ptr[wi], g_row_ptr[wi + 1], lane);
    float sc = g_dd[wi];
    g_t1h[wi * (DF / 2) + lane] = __floats2half2_rn(sc * sum.x, sc * sum.y);
}

// hop-2 + RK4 epilogue. v = -dinv_r[i] * sum_e t1h[col_e]
// MODE 1 (k1): acc  = v;  u = r + 0.5*dt*v
// MODE 2 (k2): acc += 2v; u = r + 0.5*dt*v
// MODE 3 (k3): acc += 2v; u = r +     dt*v
// MODE 4 (k4): rnext = r + dt/6*(acc + v); u = rnext (for next step's k1)
template <int MODE>
__global__ void __launch_bounds__(256)
hop2_kernel(const float* __restrict__ rin, float* __restrict__ outparam) {
    int wi = (blockIdx.x * blockDim.x + threadIdx.x) >> 5;
    if (wi >= NN) return;
    int lane = threadIdx.x & 31;
    float2 sum = row_gather(g_t1h, g_row_ptr[wi], g_row_ptr[wi + 1], lane);
    float sr = g_dinv_r[wi];
    float v0 = -sr * sum.x;
    float v1 = -sr * sum.y;

    int o = wi * (DF / 2) + lane;
    float2 r2 = ((const float2*)rin)[o];
    float p = g_premul[wi];

    if (MODE == 1) {
        g_acc[o] = make_float2(v0, v1);
        float u0 = r2.x + HALF_DT * v0, u1 = r2.y + HALF_DT * v1;
        g_uh[o] = __floats2half2_rn(p * u0, p * u1);
    } else if (MODE == 2) {
        float2 a = g_acc[o];
        g_acc[o] = make_float2(a.x + 2.0f * v0, a.y + 2.0f * v1);
        float u0 = r2.x + HALF_DT * v0, u1 = r2.y + HALF_DT * v1;
        g_uh[o] = __floats2half2_rn(p * u0, p * u1);
    } else if (MODE == 3) {
        float2 a = g_acc[o];
        g_acc[o] = make_float2(a.x + 2.0f * v0, a.y + 2.0f * v1);
        float u0 = r2.x + DTC * v0, u1 = r2.y + DTC * v1;
        g_uh[o] = __floats2half2_rn(p * u0, p * u1);
    } else {  // MODE 4
        float2 a = g_acc[o];
        float rn0 = r2.x + DT6 * (a.x + v0);
        float rn1 = r2.y + DT6 * (a.y + v1);
        ((float2*)outparam)[o] = make_float2(rn0, rn1);
        g_uh[o] = __floats2half2_rn(p * rn0, p * rn1);  // next step's k1 input
    }
}

// ---------------- launch ----------------
extern "C" void kernel_launch(void* const* d_in, const int* in_sizes, int n_in,
                              void* d_out, int out_size) {
    const float* r0   = (const float*)d_in[0];
    const int*   eidx = (const int*)d_in[1];
    const int*   mask = (const int*)d_in[2];
    const int* row = eidx;
    const int* col = eidx + NE;
    float* out = (float*)d_out;

    // CSR + normalization build
    zero_kernel      <<<(NN + 255) / 256, 256>>>();
    hist_kernel      <<<(NE + 255) / 256, 256>>>(row, col);
    dinv_kernel      <<<(NN + 255) / 256, 256>>>(mask);
    scan_block_kernel<<<NB, 1024>>>();
    scan_part_kernel <<<1, 32>>>();
    scan_add_kernel  <<<NB, 1024>>>();
    scatter_kernel   <<<(NE + 255) / 256, 256>>>(row, col);

    // slice 0 = r0; uh = premul * r0
    cudaMemcpyAsync(out, r0, (size_t)NN * DF * sizeof(float),
                    cudaMemcpyDeviceToDevice, 0);
    init_u_kernel<<<(NN * DF / 2 + 255) / 256, 256>>>(r0);

    const int blocks = (NN * 32 + 255) / 256;  // warp per row

    for (int step = 0; step < 5; step++) {
        const float* r = out + (size_t)step * NN * DF;
        float* rnext   = out + (size_t)(step + 1) * NN * DF;

        hop1_kernel   <<<blocks, 256>>>();
        hop2_kernel<1><<<blocks, 256>>>(r, nullptr);
        hop1_kernel   <<<blocks, 256>>>();
        hop2_kernel<2><<<blocks, 256>>>(r, nullptr);
        hop1_kernel   <<<blocks, 256>>>();
        hop2_kernel<3><<<blocks, 256>>>(r, nullptr);
        hop1_kernel   <<<blocks, 256>>>();
        hop2_kernel<4><<<blocks, 256>>>(r, rnext);
    }
}

// round 6
// speedup vs baseline: 1.2195x; 1.0272x over previous
#include <cuda_runtime.h>
#include <cuda_fp16.h>
#include <cstdint>

#define NN 100000
#define DF 64
#define NE 1600000
#define NB ((NN + 1023) / 1024)   // 98 scan blocks

static constexpr float DTC     = 0.2f;
static constexpr float HALF_DT = 0.1f;
static constexpr float DT6     = 0.2f / 6.0f;

// ---------------- scratch (static device globals) ----------------
__device__ int     g_deg1[NN];          // masked row degree (hop-1 CSR)
__device__ int     g_deg2[NN];          // full row degree   (hop-2 CSR)
__device__ int     g_deg_c[NN];         // full col degree
__device__ int     g_cur1[NN];
__device__ int     g_cur2[NN];
__device__ float   g_dinv_r[NN];        // row factor (applied to warp sum)
__device__ float   g_premul[NN];        // mask * dinv_c (folded into u)
__device__ float   g_dd[NN];            // dinv_r * dinv_c (folded into t1)
__device__ int     g_rp1[NN + 1];
__device__ int     g_rp2[NN + 1];
__device__ int     g_part[NB];
__device__ int     g_ecol1[NE];         // masked CSR cols (~half used)
__device__ int     g_ecol2[NE];         // full CSR cols
__device__ __half2 g_uh [NN * DF / 2];  // stage input * mask*dinv_c, fp16
__device__ __half2 g_t1h[NN * DF / 2];  // hop-1 out * dinv_r*dinv_c, fp16
__device__ float2  g_acc[NN * DF / 2];  // k1 + 2k2 + 2k3

// ---------------- preprocessing ----------------
__global__ void zero_kernel() {
    int i = blockIdx.x * blockDim.x + threadIdx.x;
    if (i < NN) { g_deg1[i] = 0; g_deg2[i] = 0; g_deg_c[i] = 0;
                  g_cur1[i] = 0; g_cur2[i] = 0; }
}

__global__ void hist_kernel(const int* __restrict__ row, const int* __restrict__ col,
                            const int* __restrict__ mask) {
    int e = blockIdx.x * blockDim.x + threadIdx.x;
    if (e < NE) {
        int r = row[e], c = col[e];
        atomicAdd(&g_deg2[r], 1);
        atomicAdd(&g_deg_c[c], 1);
        if (mask[c]) atomicAdd(&g_deg1[r], 1);
    }
}

__global__ void dinv_kernel(const int* __restrict__ mask) {
    int i = blockIdx.x * blockDim.x + threadIdx.x;
    if (i < NN) {
        int dr = g_deg2[i];
        int dc = g_deg_c[i];
        float ir = dr > 0 ? rsqrtf((float)dr) : 0.0f;
        float ic = dc > 0 ? rsqrtf((float)dc) : 0.0f;
        g_dinv_r[i] = ir;
        g_premul[i] = mask[i] ? ic : 0.0f;
        g_dd[i]     = ir * ic;
    }
}

// Two-level scan (P selects CSR 1 or 2; globals resolved in DEVICE code only)
template <int P>
__global__ void scan_block_kernel() {
    const int* __restrict__ deg = (P == 1) ? g_deg1 : g_deg2;
    int* __restrict__ rp        = (P == 1) ? g_rp1  : g_rp2;
    __shared__ int wsum[32];
    int b = blockIdx.x, t = threadIdx.x, lane = t & 31, wid = t >> 5;
    int i = b * 1024 + t;
    int v = (i < NN) ? deg[i] : 0;
    int incl = v;
    #pragma unroll
    for (int off = 1; off < 32; off <<= 1) {
        int x = __shfl_up_sync(0xffffffffu, incl, off);
        if (lane >= off) incl += x;
    }
    if (lane == 31) wsum[wid] = incl;
    __syncthreads();
    if (wid == 0) {
        int ws = wsum[lane];
        int wincl = ws;
        #pragma unroll
        for (int off = 1; off < 32; off <<= 1) {
            int x = __shfl_up_sync(0xffffffffu, wincl, off);
            if (lane >= off) wincl += x;
        }
        wsum[lane] = wincl - ws;
    }
    __syncthreads();
    int excl = incl - v + wsum[wid];
    if (i < NN) rp[i] = excl;
    if (t == 1023) g_part[b] = excl + v;
}

template <int P>
__global__ void scan_part_kernel() {
    int* __restrict__ rp = (P == 1) ? g_rp1 : g_rp2;
    if (threadIdx.x == 0) {
        int s = 0;
        for (int b = 0; b < NB; b++) { int v = g_part[b]; g_part[b] = s; s += v; }
        rp[NN] = s;
    }
}

template <int P>
__global__ void scan_add_kernel() {
    int* __restrict__ rp = (P == 1) ? g_rp1 : g_rp2;
    int i = blockIdx.x * 1024 + threadIdx.x;
    if (i < NN) rp[i] += g_part[blockIdx.x];
}

__global__ void scatter_kernel(const int* __restrict__ row, const int* __restrict__ col,
                               const int* __restrict__ mask) {
    int e = blockIdx.x * blockDim.x + threadIdx.x;
    if (e < NE) {
        int r = row[e], c = col[e];
        int p2 = g_rp2[r] + atomicAdd(&g_cur2[r], 1);
        g_ecol2[p2] = c;
        if (mask[c]) {
            int p1 = g_rp1[r] + atomicAdd(&g_cur1[r], 1);
            g_ecol1[p1] = c;
        }
    }
}

// uh = mask*dinv_c * r0  (fp16), one float2 per thread
__global__ void init_u_kernel(const float* __restrict__ r0) {
    int i = blockIdx.x * blockDim.x + threadIdx.x;   // float2 index
    if (i < NN * DF / 2) {
        int node = i >> 5;
        float p = g_premul[node];
        float2 r = ((const float2*)r0)[i];
        g_uh[i] = __floats2half2_rn(p * r.x, p * r.y);
    }
}

// ---------------- gather core: warp per row (R2-proven structure) ----------------
__device__ __forceinline__ float2
row_gather(const __half2* __restrict__ x, const int* __restrict__ ec,
           int s, int e, int lane) {
    float a0 = 0.0f, a1 = 0.0f;
    for (int base = s; base < e; base += 32) {
        int idx = base + lane;
        int c = (idx < e) ? __ldg(&ec[idx]) : 0;
        int n = min(32, e - base);
        #pragma unroll 4
        for (int j = 0; j < n; j++) {
            int cj = __shfl_sync(0xffffffffu, c, j);
            float2 f = __half22float2(__ldg(&x[cj * (DF / 2) + lane]));
            a0 += f.x;
            a1 += f.y;
        }
    }
    return make_float2(a0, a1);
}

// hop-1: t1h[i] = dd[i] * sum_{masked e} uh[col_e]  (masked CSR)
__global__ void __launch_bounds__(256)
hop1_kernel() {
    int wi = (blockIdx.x * blockDim.x + threadIdx.x) >> 5;
    if (wi >= NN) return;
    int lane = threadIdx.x & 31;
    float2 sum = row_gather(g_uh, g_ecol1, g_rp1[wi], g_rp1[wi + 1], lane);
    float sc = g_dd[wi];
    g_t1h[wi * (DF / 2) + lane] = __floats2half2_rn(sc * sum.x, sc * sum.y);
}

// hop-2 + RK4 epilogue. v = -dinv_r[i] * sum_e t1h[col_e]  (full CSR)
// MODE 1 (k1): acc  = v;  u = r + 0.5*dt*v
// MODE 2 (k2): acc += 2v; u = r + 0.5*dt*v
// MODE 3 (k3): acc += 2v; u = r +     dt*v
// MODE 4 (k4): rnext = r + dt/6*(acc + v); u = rnext
template <int MODE>
__global__ void __launch_bounds__(256)
hop2_kernel(const float* __restrict__ rin, float* __restrict__ outparam) {
    int wi = (blockIdx.x * blockDim.x + threadIdx.x) >> 5;
    if (wi >= NN) return;
    int lane = threadIdx.x & 31;
    float2 sum = row_gather(g_t1h, g_ecol2, g_rp2[wi], g_rp2[wi + 1], lane);
    float sr = g_dinv_r[wi];
    float v0 = -sr * sum.x;
    float v1 = -sr * sum.y;

    int o = wi * (DF / 2) + lane;
    float2 r2 = ((const float2*)rin)[o];
    float p = g_premul[wi];

    if (MODE == 1) {
        g_acc[o] = make_float2(v0, v1);
        float u0 = r2.x + HALF_DT * v0, u1 = r2.y + HALF_DT * v1;
        g_uh[o] = __floats2half2_rn(p * u0, p * u1);
    } else if (MODE == 2) {
        float2 a = g_acc[o];
        g_acc[o] = make_float2(a.x + 2.0f * v0, a.y + 2.0f * v1);
        float u0 = r2.x + HALF_DT * v0, u1 = r2.y + HALF_DT * v1;
        g_uh[o] = __floats2half2_rn(p * u0, p * u1);
    } else if (MODE == 3) {
        float2 a = g_acc[o];
        g_acc[o] = make_float2(a.x + 2.0f * v0, a.y + 2.0f * v1);
        float u0 = r2.x + DTC * v0, u1 = r2.y + DTC * v1;
        g_uh[o] = __floats2half2_rn(p * u0, p * u1);
    } else {  // MODE 4
        float2 a = g_acc[o];
        float rn0 = r2.x + DT6 * (a.x + v0);
        float rn1 = r2.y + DT6 * (a.y + v1);
        ((float2*)outparam)[o] = make_float2(rn0, rn1);
        g_uh[o] = __floats2half2_rn(p * rn0, p * rn1);  // next step's k1 input
    }
}

// ---------------- launch ----------------
extern "C" void kernel_launch(void* const* d_in, const int* in_sizes, int n_in,
                              void* d_out, int out_size) {
    const float* r0   = (const float*)d_in[0];
    const int*   eidx = (const int*)d_in[1];
    const int*   mask = (const int*)d_in[2];
    const int* row = eidx;
    const int* col = eidx + NE;
    float* out = (float*)d_out;

    // CSR + normalization build (no device-global symbols passed from host!)
    zero_kernel<<<(NN + 255) / 256, 256>>>();
    hist_kernel<<<(NE + 255) / 256, 256>>>(row, col, mask);
    dinv_kernel<<<(NN + 255) / 256, 256>>>(mask);
    scan_block_kernel<1><<<NB, 1024>>>();
    scan_part_kernel <1><<<1, 32>>>();
    scan_add_kernel  <1><<<NB, 1024>>>();
    scan_block_kernel<2><<<NB, 1024>>>();
    scan_part_kernel <2><<<1, 32>>>();
    scan_add_kernel  <2><<<NB, 1024>>>();
    scatter_kernel   <<<(NE + 255) / 256, 256>>>(row, col, mask);

    // slice 0 = r0; uh = premul * r0
    cudaMemcpyAsync(out, r0, (size_t)NN * DF * sizeof(float),
                    cudaMemcpyDeviceToDevice, 0);
    init_u_kernel<<<(NN * DF / 2 + 255) / 256, 256>>>(r0);

    const int blocks = (NN * 32 + 255) / 256;  // warp per row

    for (int step = 0; step < 5; step++) {
        const float* r = out + (size_t)step * NN * DF;
        float* rnext   = out + (size_t)(step + 1) * NN * DF;

        hop1_kernel   <<<blocks, 256>>>();
        hop2_kernel<1><<<blocks, 256>>>(r, nullptr);
        hop1_kernel   <<<blocks, 256>>>();
        hop2_kernel<2><<<blocks, 256>>>(r, nullptr);
        hop1_kernel   <<<blocks, 256>>>();
        hop2_kernel<3><<<blocks, 256>>>(r, nullptr);
        hop1_kernel   <<<blocks, 256>>>();
        hop2_kernel<4><<<blocks, 256>>>(r, rnext);
    }
}